// round 2
// baseline (speedup 1.0000x reference)
#include <cuda_runtime.h>
#include <cuda_bf16.h>
#include <cstdint>

// ============================================================================
// IsingRBM: psi[m] = prod_h cos(bias[h] + (x@W1)[m,h] + 0.5 * x^T W2[h] x)
// Fused GEMM via mma.sync.m16n8k16 bf16 (baseline PTX — harness compiles
// through compute_103, so no tcgen05 available).
// K = 64*64 (quadratic) + 64 (linear) = 4160, in 65 chunks of 64.
// A-chunk i = x-tile row-scaled by x[:,i]; scaling done on register-resident
// bf16 A-base fragments via mul.bf16x2 — A never goes through smem in-loop.
// B pre-converted to bf16 once (prep kernel), streamed via cp.async (3 bufs).
// ============================================================================

static constexpr int kV = 64;
static constexpr int kH = 128;
static constexpr int kMTile = 128;
static constexpr int kChunks = 65;
static constexpr int kChunkBytes = kH * kV * 2;   // 16384
static constexpr int kThreads = 256;

// smem layout (bytes, relative to 1024-aligned base)
static constexpr int SM_BIAS = 0;                  // 128 f32
static constexpr int SM_PART = 512;                // 128*4 f32
static constexpr int SM_XST  = 2560;               // 64*129 f32 = 33024
static constexpr int SM_XT   = 36864;              // 128x64 bf16 SW128 = 16384
static constexpr int SM_B    = 53248;              // 3 * 16384
static constexpr int SM_END  = SM_B + 3 * kChunkBytes;   // 102400
static constexpr int SMEM_TOTAL = SM_END + 1024;

// Pre-converted B operand: [chunk][h][j] bf16. chunk<64: W2[h][chunk][j];
// chunk 64: 2*W1^T (so the 0.5 epilogue scale yields exactly x@W1).
__device__ __align__(16) __nv_bfloat16 g_wb[kChunks * kH * kV];

// ---------------------------------------------------------------------------
// PTX helpers (baseline PTX only)
// ---------------------------------------------------------------------------
__device__ __forceinline__ uint32_t smem_u32(const void* p) {
    uint32_t a;
    asm("{ .reg .u64 t; cvta.to.shared.u64 t, %1; cvt.u32.u64 %0, t; }"
        : "=r"(a) : "l"(p));
    return a;
}

#define SW128(o) ((o) ^ (((o) >> 3) & 0x70))

// pack: lo = a, hi = b
#define CVT_BF16X2(result, a, b) \
    asm("cvt.rn.bf16x2.f32 %0, %1, %2;" : "=r"(result) : "f"(b), "f"(a))

#define HMUL2(d, a, b) \
    asm("mul.rn.bf16x2 %0, %1, %2;" : "=r"(d) : "r"(a), "r"(b))

#define LDSM_X4(r0, r1, r2, r3, addr) \
    asm volatile("ldmatrix.sync.aligned.m8n8.x4.shared.b16 {%0,%1,%2,%3}, [%4];" \
        : "=r"(r0), "=r"(r1), "=r"(r2), "=r"(r3) : "r"(addr))

#define MMA16816(d, a0, a1, a2, a3, b0, b1) \
    asm volatile("mma.sync.aligned.m16n8k16.row.col.f32.bf16.bf16.f32 " \
        "{%0,%1,%2,%3}, {%4,%5,%6,%7}, {%8,%9}, {%0,%1,%2,%3};" \
        : "+f"((d)[0]), "+f"((d)[1]), "+f"((d)[2]), "+f"((d)[3]) \
        : "r"(a0), "r"(a1), "r"(a2), "r"(a3), "r"(b0), "r"(b1))

#define CP_ASYNC16(smem, gmem) \
    asm volatile("cp.async.cg.shared.global [%0], [%1], 16;" \
        :: "r"(smem), "l"(gmem) : "memory")
#define CP_COMMIT() asm volatile("cp.async.commit_group;" ::: "memory")
#define CP_WAIT1()  asm volatile("cp.async.wait_group 1;" ::: "memory")

__device__ __forceinline__ float cos_poly(float a) {
    // |a| < 0.1 guaranteed by problem statistics; deg-8 Taylor, err < 1e-12
    float t = a * a;
    return 1.0f + t * (-0.5f + t * (4.16666667e-2f +
               t * (-1.38888889e-3f + t * 2.48015873e-5f)));
}

// ---------------------------------------------------------------------------
// prep: convert W2 (f32) + 2*W1^T (f32) into bf16 B-operand buffer g_wb
// ---------------------------------------------------------------------------
__global__ void __launch_bounds__(256) prep_kernel(const float* __restrict__ w2,
                                                   const float* __restrict__ w1) {
    int t = blockIdx.x * blockDim.x + threadIdx.x;   // one uint2 (4 bf16) each
    int e = t * 4;
    if (e >= kChunks * kH * kV) return;
    int i   = e >> 13;          // chunk
    int rem = e & 8191;
    int h   = rem >> 6;
    int j   = rem & 63;         // multiple of 4
    float v0, v1, v2, v3;
    if (i < 64) {
        const float4 f = *reinterpret_cast<const float4*>(w2 + h * 4096 + i * 64 + j);
        v0 = f.x; v1 = f.y; v2 = f.z; v3 = f.w;
    } else {
        v0 = 2.0f * w1[(j + 0) * kH + h];
        v1 = 2.0f * w1[(j + 1) * kH + h];
        v2 = 2.0f * w1[(j + 2) * kH + h];
        v3 = 2.0f * w1[(j + 3) * kH + h];
    }
    uint32_t lo, hi;
    CVT_BF16X2(lo, v0, v1);
    CVT_BF16X2(hi, v2, v3);
    reinterpret_cast<uint2*>(g_wb)[t] = make_uint2(lo, hi);
}

// ---------------------------------------------------------------------------
// main fused kernel: one 128-row M-tile per CTA, full H=128 as N
// warp grid 2(M) x 4(N): warp tile 64 x 32
// ---------------------------------------------------------------------------
__global__ void __launch_bounds__(kThreads, 1)
rbm_main_kernel(const float* __restrict__ x,
                const float* __restrict__ bias,
                float* __restrict__ out) {
    extern __shared__ char smem_raw[];
    char* sm = (char*)((((uintptr_t)smem_raw) + 1023) & ~(uintptr_t)1023);
    const uint32_t sb = smem_u32(sm);
    const int tid = threadIdx.x;
    const int l   = tid & 31;
    const int w   = tid >> 5;
    const int g   = l >> 2;            // mma group id (0..7)
    const int t4  = l & 3;
    const int wm  = (w >> 2) * 64;     // warp M offset (0 or 64)
    const int wn  = (w & 3) * 32;      // warp N offset (0,32,64,96)
    const int m0  = blockIdx.x * kMTile;

    float* sbias = (float*)(sm + SM_BIAS);
    float* spart = (float*)(sm + SM_PART);
    float* xst   = (float*)(sm + SM_XST);     // [j][m] f32, pitch 129

    if (tid < kH) sbias[tid] = bias[tid];

    // --- x bf16 tile [m][j], 128B rows, SW128 swizzled ---
    {
        const float4* x4 = (const float4*)(x + (size_t)m0 * kV);
        #pragma unroll
        for (int e = tid; e < 2048; e += kThreads) {   // 128 rows * 16 float4
            int r = e >> 4, q = e & 15;
            float4 f = x4[e];
            uint32_t u0, u1;
            CVT_BF16X2(u0, f.x, f.y);
            CVT_BF16X2(u1, f.z, f.w);
            uint32_t off = (uint32_t)(r * 128 + q * 8);
            *(uint2*)(sm + SM_XT + SW128(off)) = make_uint2(u0, u1);
        }
    }
    // --- x f32 transposed (for per-chunk row scalars) ---
    for (int e = tid; e < kMTile * kV; e += kThreads) {
        int m = e >> 6, j = e & 63;
        xst[j * 129 + m] = x[(size_t)(m0 + m) * kV + j];
    }

    // --- cp.async B prefetch (3 buffers, distance 2) ---
    const char* gw = (const char*)g_wb;
    #define ISSUE_CHUNK(c, buf) do {                                          \
        const char* _src = gw + (size_t)(c) * kChunkBytes;                    \
        uint32_t _dst = sb + SM_B + (uint32_t)(buf) * kChunkBytes;            \
        _Pragma("unroll")                                                     \
        for (int _p = 0; _p < 4; _p++) {                                      \
            int _cg = tid + _p * 256;                                         \
            uint32_t _off = (uint32_t)((_cg >> 3) * 128 + (_cg & 7) * 16);    \
            CP_ASYNC16(_dst + SW128(_off), _src + _off);                      \
        }                                                                     \
    } while (0)

    ISSUE_CHUNK(0, 0); CP_COMMIT();
    ISSUE_CHUNK(1, 1); CP_COMMIT();

    __syncthreads();   // x tiles + bias ready

    // --- A-base fragments (warp's 64x64 x-tile) held in registers ---
    uint32_t abase[64];
    {
        int q = l >> 3, rr = l & 7;
        #pragma unroll
        for (int mb = 0; mb < 4; mb++)
        #pragma unroll
        for (int kb = 0; kb < 4; kb++) {
            uint32_t off = (uint32_t)((wm + 16 * mb + (q & 1) * 8 + rr) * 128
                                      + (kb * 16 + (q >> 1) * 8) * 2);
            int bse = (mb * 4 + kb) * 4;
            LDSM_X4(abase[bse], abase[bse + 1], abase[bse + 2], abase[bse + 3],
                    sb + SM_XT + SW128(off));
        }
    }

    // --- per-thread B ldmatrix offsets (swizzled, relative to buffer base) ---
    uint32_t boff[8];
    {
        int q = l >> 3, rr = l & 7;
        #pragma unroll
        for (int kb = 0; kb < 4; kb++)
        #pragma unroll
        for (int nb2 = 0; nb2 < 2; nb2++) {
            uint32_t off = (uint32_t)((wn + nb2 * 16 + (q >> 1) * 8 + rr) * 128
                                      + (kb * 16 + (q & 1) * 8) * 2);
            boff[kb * 2 + nb2] = SW128(off);
        }
    }

    float acc[4][4][4];
    #pragma unroll
    for (int a = 0; a < 4; a++)
    #pragma unroll
    for (int b = 0; b < 4; b++)
    #pragma unroll
    for (int c = 0; c < 4; c++) acc[a][b][c] = 0.0f;

    const int rbase0 = wm + g;

    for (int i = 0; i < kChunks; i++) {
        // row scalars x[r, i] as broadcast bf16x2 (chunk 64: scale = 1)
        uint32_t svec[8];
        if (i < 64) {
            #pragma unroll
            for (int mb = 0; mb < 4; mb++) {
                float f0 = xst[i * 129 + rbase0 + 16 * mb];
                float f1 = xst[i * 129 + rbase0 + 16 * mb + 8];
                CVT_BF16X2(svec[2 * mb],     f0, f0);
                CVT_BF16X2(svec[2 * mb + 1], f1, f1);
            }
        } else {
            #pragma unroll
            for (int k2 = 0; k2 < 8; k2++) svec[k2] = 0x3F803F80u;  // 1.0,1.0
        }

        CP_WAIT1();          // chunk i landed
        __syncthreads();     // all warps done with buffer (i-1)%3, data visible
        if (i + 2 < kChunks) { ISSUE_CHUNK(i + 2, (i + 2) % 3); }
        CP_COMMIT();

        uint32_t bb = sb + SM_B + (uint32_t)(i % 3) * kChunkBytes;
        #pragma unroll
        for (int kb = 0; kb < 4; kb++) {
            uint32_t bf[4][2];
            LDSM_X4(bf[0][0], bf[0][1], bf[1][0], bf[1][1], bb + boff[kb * 2 + 0]);
            LDSM_X4(bf[2][0], bf[2][1], bf[3][0], bf[3][1], bb + boff[kb * 2 + 1]);
            #pragma unroll
            for (int mb = 0; mb < 4; mb++) {
                int ab = (mb * 4 + kb) * 4;
                uint32_t t0, t1, t2, t3;
                HMUL2(t0, abase[ab + 0], svec[2 * mb]);      // rows g
                HMUL2(t1, abase[ab + 1], svec[2 * mb + 1]);  // rows g+8
                HMUL2(t2, abase[ab + 2], svec[2 * mb]);
                HMUL2(t3, abase[ab + 3], svec[2 * mb + 1]);
                #pragma unroll
                for (int nb = 0; nb < 4; nb++)
                    MMA16816(acc[mb][nb], t0, t1, t2, t3, bf[nb][0], bf[nb][1]);
            }
        }
    }

    // --- epilogue: a = bias + 0.5*acc; psi = prod cos(a) ---
    #pragma unroll
    for (int mb = 0; mb < 4; mb++) {
        float p0 = 1.0f, p1 = 1.0f;
        #pragma unroll
        for (int nb = 0; nb < 4; nb++) {
            int col = wn + nb * 8 + 2 * t4;
            #pragma unroll
            for (int c = 0; c < 2; c++) {
                float bv = sbias[col + c];
                p0 *= cos_poly(bv + 0.5f * acc[mb][nb][c]);       // row g
                p1 *= cos_poly(bv + 0.5f * acc[mb][nb][2 + c]);   // row g+8
            }
        }
        // reduce over the quad (t4 = 0..3) -> product over this warp's 32 cols
        p0 *= __shfl_xor_sync(0xFFFFFFFFu, p0, 1);
        p0 *= __shfl_xor_sync(0xFFFFFFFFu, p0, 2);
        p1 *= __shfl_xor_sync(0xFFFFFFFFu, p1, 1);
        p1 *= __shfl_xor_sync(0xFFFFFFFFu, p1, 2);
        if (t4 == 0) {
            spart[(rbase0 + 16 * mb) * 4 + (w & 3)]     = p0;
            spart[(rbase0 + 16 * mb + 8) * 4 + (w & 3)] = p1;
        }
    }
    __syncthreads();
    if (tid < kMTile) {
        float pr = spart[tid * 4 + 0] * spart[tid * 4 + 1]
                 * spart[tid * 4 + 2] * spart[tid * 4 + 3];
        out[m0 + tid] = pr;
    }
}

// ---------------------------------------------------------------------------
// launch
// ---------------------------------------------------------------------------
extern "C" void kernel_launch(void* const* d_in, const int* in_sizes, int n_in,
                              void* d_out, int out_size) {
    const float* x    = (const float*)d_in[0];   // (16384, 64)
    const float* w1   = (const float*)d_in[1];   // (64, 128)
    const float* w2   = (const float*)d_in[2];   // (128, 64, 64)
    const float* bias = (const float*)d_in[3];   // (128,)
    float* out = (float*)d_out;                  // (16384,)

    cudaFuncSetAttribute(rbm_main_kernel,
                         cudaFuncAttributeMaxDynamicSharedMemorySize, SMEM_TOTAL);

    prep_kernel<<<520, 256>>>(w2, w1);           // 65*8192/4/256
    rbm_main_kernel<<<16384 / kMTile, kThreads, SMEM_TOTAL>>>(x, bias, out);
}

// round 3
// speedup vs baseline: 1.2053x; 1.2053x over previous
#include <cuda_runtime.h>
#include <cuda_bf16.h>
#include <cstdint>

// ============================================================================
// IsingRBM: psi[m] = prod_h cos(bias[h] + (x@W1)[m,h] + 0.5 * x^T W2[h] x)
// mma.sync.m16n8k16 bf16 (compute_103 baseline PTX; tcgen05 unavailable).
//
// R3: symmetric K-packing. Quadratic term folded to upper triangle with
// W2[i,j]+W2[j,i] weights; row i padded to 16-aligned j-start so each k16
// block has a single (scale-row i, A-fragment kbf) pair:
//   i in [ 0,16): kbf 0,1,2,3   (4 blocks)   blocks [  0, 64)
//   i in [16,32): kbf 1,2,3     (3 blocks)   blocks [ 64,112)
//   i in [32,48): kbf 2,3       (2 blocks)   blocks [112,144)
//   i in [48,64): kbf 3         (1 block )   blocks [144,160)
//   linear (2*W1^T, scale=1):   kbf 0,1,2,3  blocks [160,164)
// 164 blocks = 41 chunks of 64 k (vs 65 chunks unpacked) -> 0.63x tensor work.
// 512 threads (16 warps, 4Mx4N grid, 32x32 warp tiles) to feed the HMMA pipe.
// ============================================================================

static constexpr int kV = 64;
static constexpr int kH = 128;
static constexpr int kMTile = 128;
static constexpr int kChunks = 41;
static constexpr int kChunkBytes = kH * kV * 2;   // 16384
static constexpr int kThreads = 512;

// smem layout (bytes, relative to 1024-aligned base)
static constexpr int SM_BIAS = 0;                  // 128 f32
static constexpr int SM_PART = 512;                // 128*4 f32
static constexpr int SM_XS2  = 2560;               // 64*129 u32 (bf16x2 bcast) = 33024
static constexpr int SM_XT   = 36864;              // 128x64 bf16 SW128 = 16384 (1024-aligned)
static constexpr int SM_B    = 53248;              // 3 * 16384 (1024-aligned)
static constexpr int SM_END  = SM_B + 3 * kChunkBytes;   // 102400
static constexpr int SMEM_TOTAL = SM_END + 1024;

// Packed B operand: [chunk][h][64] bf16, cols = 4 k16-blocks per chunk.
__device__ __align__(16) __nv_bfloat16 g_wb[kChunks * kH * kV];

// ---------------------------------------------------------------------------
// helpers
// ---------------------------------------------------------------------------
__device__ __forceinline__ uint32_t smem_u32(const void* p) {
    uint32_t a;
    asm("{ .reg .u64 t; cvta.to.shared.u64 t, %1; cvt.u32.u64 %0, t; }"
        : "=r"(a) : "l"(p));
    return a;
}

#define SW128(o) ((o) ^ (((o) >> 3) & 0x70))

#define CVT_BF16X2(result, a, b) \
    asm("cvt.rn.bf16x2.f32 %0, %1, %2;" : "=r"(result) : "f"(b), "f"(a))

#define HMUL2(d, a, b) \
    asm("mul.rn.bf16x2 %0, %1, %2;" : "=r"(d) : "r"(a), "r"(b))

#define LDSM_X4(r0, r1, r2, r3, addr) \
    asm volatile("ldmatrix.sync.aligned.m8n8.x4.shared.b16 {%0,%1,%2,%3}, [%4];" \
        : "=r"(r0), "=r"(r1), "=r"(r2), "=r"(r3) : "r"(addr))

#define MMA16816(d, a0, a1, a2, a3, b0, b1) \
    asm volatile("mma.sync.aligned.m16n8k16.row.col.f32.bf16.bf16.f32 " \
        "{%0,%1,%2,%3}, {%4,%5,%6,%7}, {%8,%9}, {%0,%1,%2,%3};" \
        : "+f"((d)[0]), "+f"((d)[1]), "+f"((d)[2]), "+f"((d)[3]) \
        : "r"(a0), "r"(a1), "r"(a2), "r"(a3), "r"(b0), "r"(b1))

#define CP_ASYNC16(smem, gmem) \
    asm volatile("cp.async.cg.shared.global [%0], [%1], 16;" \
        :: "r"(smem), "l"(gmem) : "memory")
#define CP_COMMIT() asm volatile("cp.async.commit_group;" ::: "memory")
#define CP_WAIT1()  asm volatile("cp.async.wait_group 1;" ::: "memory")

__device__ __forceinline__ float cos_poly(float a) {
    // |a| < 0.1 guaranteed by problem statistics; deg-8 Taylor, err < 1e-12
    float t = a * a;
    return 1.0f + t * (-0.5f + t * (4.16666667e-2f +
               t * (-1.38888889e-3f + t * 2.48015873e-5f)));
}

// block schedule decode (see header comment)
__device__ __forceinline__ int decode_i(int b) {
    if (b < 64)  return b >> 2;
    if (b < 112) return 16 + (b - 64) / 3;
    if (b < 144) return 32 + ((b - 112) >> 1);
    if (b < 160) return 48 + (b - 144);
    return 64;   // linear term marker
}
__device__ __forceinline__ int decode_kbf(int b) {
    if (b < 64)  return b & 3;
    if (b < 112) return 1 + (b - 64) % 3;
    if (b < 144) return 2 + ((b - 112) & 1);
    if (b < 160) return 3;
    return b - 160;
}

// ---------------------------------------------------------------------------
// prep: build packed bf16 B operand g_wb from W2 (f32) + 2*W1^T (f32)
// ---------------------------------------------------------------------------
__global__ void __launch_bounds__(256) prep_kernel(const float* __restrict__ w2,
                                                   const float* __restrict__ w1) {
    int t = blockIdx.x * blockDim.x + threadIdx.x;
    int e = t * 4;
    if (e >= kChunks * kH * kV) return;
    int c   = e >> 13;
    int rem = e & 8191;
    int h   = rem >> 6;
    int col = rem & 63;                 // 4-aligned, stays within one k16 block
    int b   = 4 * c + (col >> 4);
    int i   = decode_i(b);
    int kbf = decode_kbf(b);
    int j0  = kbf * 16 + (col & 15);
    float v[4];
    #pragma unroll
    for (int q = 0; q < 4; q++) {
        int j = j0 + q;
        if (i == 64)     v[q] = 2.0f * w1[j * kH + h];
        else if (j > i)  v[q] = w2[h * 4096 + i * 64 + j] + w2[h * 4096 + j * 64 + i];
        else if (j == i) v[q] = w2[h * 4096 + i * 64 + j];
        else             v[q] = 0.0f;   // padding inside leading 16-block
    }
    uint32_t lo, hi;
    CVT_BF16X2(lo, v[0], v[1]);
    CVT_BF16X2(hi, v[2], v[3]);
    reinterpret_cast<uint2*>(g_wb)[t] = make_uint2(lo, hi);
}

// ---------------------------------------------------------------------------
// chunk body, templated on the 4 A-fragment indices (compile-time reg index)
// ---------------------------------------------------------------------------
template<int F0, int F1, int F2, int F3>
__device__ __forceinline__ void do_chunk(
    int c, uint32_t bb, const uint32_t* __restrict__ boff,
    const uint32_t (&abase)[2][4][4],
    const uint32_t* __restrict__ xs2, int rb0,
    float (&acc)[2][4][4])
{
    const int frg[4] = {F0, F1, F2, F3};
    #pragma unroll
    for (int kb = 0; kb < 4; kb++) {
        const int b   = 4 * c + kb;
        const int isc = decode_i(b);
        const int ii  = (isc < 64) ? isc : 0;     // keep smem reads in-bounds
        uint32_t sv[4];
        #pragma unroll
        for (int mb = 0; mb < 2; mb++) {
            uint32_t u0 = xs2[ii * 129 + rb0 + 16 * mb];
            uint32_t u1 = xs2[ii * 129 + rb0 + 16 * mb + 8];
            sv[2 * mb]     = (isc < 64) ? u0 : 0x3F803F80u;   // 1.0,1.0 bf16x2
            sv[2 * mb + 1] = (isc < 64) ? u1 : 0x3F803F80u;
        }
        uint32_t bf[4][2];
        LDSM_X4(bf[0][0], bf[0][1], bf[1][0], bf[1][1], bb + boff[kb * 2 + 0]);
        LDSM_X4(bf[2][0], bf[2][1], bf[3][0], bf[3][1], bb + boff[kb * 2 + 1]);
        #pragma unroll
        for (int mb = 0; mb < 2; mb++) {
            uint32_t t0, t1, t2, t3;
            HMUL2(t0, abase[mb][frg[kb]][0], sv[2 * mb]);      // rows g
            HMUL2(t1, abase[mb][frg[kb]][1], sv[2 * mb + 1]);  // rows g+8
            HMUL2(t2, abase[mb][frg[kb]][2], sv[2 * mb]);
            HMUL2(t3, abase[mb][frg[kb]][3], sv[2 * mb + 1]);
            #pragma unroll
            for (int nb = 0; nb < 4; nb++)
                MMA16816(acc[mb][nb], t0, t1, t2, t3, bf[nb][0], bf[nb][1]);
        }
    }
}

// ---------------------------------------------------------------------------
// main fused kernel: 128-row M-tile per CTA, H=128 as N, 16 warps (4M x 4N)
// ---------------------------------------------------------------------------
__global__ void __launch_bounds__(kThreads, 1)
rbm_main_kernel(const float* __restrict__ x,
                const float* __restrict__ bias,
                float* __restrict__ out) {
    extern __shared__ char smem_raw[];
    char* sm = (char*)((((uintptr_t)smem_raw) + 1023) & ~(uintptr_t)1023);
    const uint32_t sb = smem_u32(sm);
    const int tid = threadIdx.x;
    const int l   = tid & 31;
    const int w   = tid >> 5;
    const int g   = l >> 2;
    const int t4  = l & 3;
    const int wm  = (w >> 2) * 32;     // warp M offset (0,32,64,96)
    const int wn  = (w & 3) * 32;      // warp N offset (0,32,64,96)
    const int m0  = blockIdx.x * kMTile;

    float*    sbias = (float*)(sm + SM_BIAS);
    float*    spart = (float*)(sm + SM_PART);
    uint32_t* xs2   = (uint32_t*)(sm + SM_XS2);   // [j][m] bf16x2 broadcast, pitch 129

    if (tid < kH) sbias[tid] = bias[tid];

    // --- x bf16 tile [m][j], 128B rows, SW128 swizzled (A ldmatrix source) ---
    {
        const float4* x4 = (const float4*)(x + (size_t)m0 * kV);
        #pragma unroll
        for (int e = tid; e < 2048; e += kThreads) {
            int r = e >> 4, q = e & 15;
            float4 f = x4[e];
            uint32_t u0, u1;
            CVT_BF16X2(u0, f.x, f.y);
            CVT_BF16X2(u1, f.z, f.w);
            uint32_t off = (uint32_t)(r * 128 + q * 8);
            *(uint2*)(sm + SM_XT + SW128(off)) = make_uint2(u0, u1);
        }
    }
    // --- xs2[j][m] = bf16x2(x[m,j], x[m,j]) broadcast scalars ---
    #pragma unroll
    for (int e = tid; e < kV * kMTile; e += kThreads) {
        int m = e >> 6, j = e & 63;
        float v = x[(size_t)(m0 + m) * kV + j];
        uint32_t p;
        CVT_BF16X2(p, v, v);
        xs2[j * 129 + m] = p;
    }

    // --- cp.async B prefetch (3 buffers, distance 2) ---
    const char* gw = (const char*)g_wb;
    #define ISSUE_CHUNK(c, buf) do {                                          \
        const char* _src = gw + (size_t)(c) * kChunkBytes;                    \
        uint32_t _dst = sb + SM_B + (uint32_t)(buf) * kChunkBytes;            \
        _Pragma("unroll")                                                     \
        for (int _p = 0; _p < 2; _p++) {                                      \
            int _cg = tid + _p * kThreads;                                    \
            uint32_t _off = (uint32_t)((_cg >> 3) * 128 + (_cg & 7) * 16);    \
            CP_ASYNC16(_dst + SW128(_off), _src + _off);                      \
        }                                                                     \
    } while (0)

    ISSUE_CHUNK(0, 0); CP_COMMIT();
    ISSUE_CHUNK(1, 1); CP_COMMIT();

    __syncthreads();   // x tiles + bias ready

    // --- A-base fragments (warp's 32x64 x-tile) in registers ---
    uint32_t abase[2][4][4];
    {
        int q = l >> 3, rr = l & 7;
        #pragma unroll
        for (int mb = 0; mb < 2; mb++)
        #pragma unroll
        for (int kb = 0; kb < 4; kb++) {
            uint32_t off = (uint32_t)((wm + 16 * mb + (q & 1) * 8 + rr) * 128
                                      + (kb * 16 + (q >> 1) * 8) * 2);
            LDSM_X4(abase[mb][kb][0], abase[mb][kb][1],
                    abase[mb][kb][2], abase[mb][kb][3],
                    sb + SM_XT + SW128(off));
        }
    }

    // --- per-thread B ldmatrix offsets (swizzled, relative to buffer base) ---
    uint32_t boff[8];
    {
        int q = l >> 3, rr = l & 7;
        #pragma unroll
        for (int kb = 0; kb < 4; kb++)
        #pragma unroll
        for (int nb2 = 0; nb2 < 2; nb2++) {
            uint32_t off = (uint32_t)((wn + nb2 * 16 + (q >> 1) * 8 + rr) * 128
                                      + (kb * 16 + (q & 1) * 8) * 2);
            boff[kb * 2 + nb2] = SW128(off);
        }
    }

    float acc[2][4][4];
    #pragma unroll
    for (int a = 0; a < 2; a++)
    #pragma unroll
    for (int b = 0; b < 4; b++)
    #pragma unroll
    for (int c = 0; c < 4; c++) acc[a][b][c] = 0.0f;

    const int rb0 = wm + g;

    for (int c = 0; c < kChunks; c++) {
        CP_WAIT1();          // chunk c landed
        __syncthreads();     // all warps done with buffer (c+2)%3, data visible
        if (c + 2 < kChunks) { ISSUE_CHUNK(c + 2, (c + 2) % 3); }
        CP_COMMIT();

        uint32_t bb = sb + SM_B + (uint32_t)(c % 3) * kChunkBytes;

        // A-fragment pattern per chunk (static schedule)
        int pat;
        if (c < 16 || c == 40) pat = 0;
        else if (c < 28)       pat = 1 + (c - 16) % 3;
        else if (c < 36)       pat = 4;
        else                   pat = 5;

        switch (pat) {
        case 0: do_chunk<0,1,2,3>(c, bb, boff, abase, xs2, rb0, acc); break;
        case 1: do_chunk<1,2,3,1>(c, bb, boff, abase, xs2, rb0, acc); break;
        case 2: do_chunk<2,3,1,2>(c, bb, boff, abase, xs2, rb0, acc); break;
        case 3: do_chunk<3,1,2,3>(c, bb, boff, abase, xs2, rb0, acc); break;
        case 4: do_chunk<2,3,2,3>(c, bb, boff, abase, xs2, rb0, acc); break;
        default: do_chunk<3,3,3,3>(c, bb, boff, abase, xs2, rb0, acc); break;
        }
    }

    // --- epilogue: a = bias + 0.5*acc; psi = prod cos(a) ---
    #pragma unroll
    for (int mb = 0; mb < 2; mb++) {
        float p0 = 1.0f, p1 = 1.0f;
        #pragma unroll
        for (int nb = 0; nb < 4; nb++) {
            int col = wn + nb * 8 + 2 * t4;
            #pragma unroll
            for (int cc = 0; cc < 2; cc++) {
                float bv = sbias[col + cc];
                p0 *= cos_poly(bv + 0.5f * acc[mb][nb][cc]);       // row g
                p1 *= cos_poly(bv + 0.5f * acc[mb][nb][2 + cc]);   // row g+8
            }
        }
        p0 *= __shfl_xor_sync(0xFFFFFFFFu, p0, 1);
        p0 *= __shfl_xor_sync(0xFFFFFFFFu, p0, 2);
        p1 *= __shfl_xor_sync(0xFFFFFFFFu, p1, 1);
        p1 *= __shfl_xor_sync(0xFFFFFFFFu, p1, 2);
        if (t4 == 0) {
            spart[(rb0 + 16 * mb) * 4 + (w & 3)]     = p0;
            spart[(rb0 + 16 * mb + 8) * 4 + (w & 3)] = p1;
        }
    }
    __syncthreads();
    if (tid < kMTile) {
        out[m0 + tid] = spart[tid * 4 + 0] * spart[tid * 4 + 1]
                      * spart[tid * 4 + 2] * spart[tid * 4 + 3];
    }
}

// ---------------------------------------------------------------------------
// launch
// ---------------------------------------------------------------------------
extern "C" void kernel_launch(void* const* d_in, const int* in_sizes, int n_in,
                              void* d_out, int out_size) {
    const float* x    = (const float*)d_in[0];   // (16384, 64)
    const float* w1   = (const float*)d_in[1];   // (64, 128)
    const float* w2   = (const float*)d_in[2];   // (128, 64, 64)
    const float* bias = (const float*)d_in[3];   // (128,)
    float* out = (float*)d_out;                  // (16384,)

    cudaFuncSetAttribute(rbm_main_kernel,
                         cudaFuncAttributeMaxDynamicSharedMemorySize, SMEM_TOTAL);

    // 41*8192 elems / 4 per thread / 256 per block = 328 blocks
    prep_kernel<<<328, 256>>>(w2, w1);
    rbm_main_kernel<<<16384 / kMTile, kThreads, SMEM_TOTAL>>>(x, bias, out);
}

// round 4
// speedup vs baseline: 1.4566x; 1.2085x over previous
#include <cuda_runtime.h>
#include <cuda_bf16.h>
#include <cstdint>

// ============================================================================
// IsingRBM: psi[m] = prod_h cos(bias[h] + (x@W1)[m,h] + 0.5 * x^T W2[h] x)
// mma.sync.m16n8k16 bf16 (compute_103 baseline PTX; tcgen05 unavailable).
//
// Symmetric K-packing (upper triangle, rows 16-aligned): 164 k16-blocks in
// 41 chunks of 64 k.  Block schedule is periodic per region and is baked in
// at compile time: do_chunk is templated on the kbf pattern AND the i-delta
// pattern; a running ibase register replaces all runtime decode (R3 had an
// integer divide in the inner loop -> 21% alu pipe).
//   A: c  0..15  kbf<0,1,2,3> di<0,0,0,0>  ibase=c        (i = c)
//   B: c 16..27  3-chunk period, ibase += 4 per period    (i = 16..31)
//   C: c 28..35  kbf<2,3,2,3> di<0,0,1,1>  ibase += 2     (i = 32..47)
//   D: c 36..39  kbf<3,3,3,3> di<0,1,2,3>  ibase += 4     (i = 48..63)
//   E: c 40      linear term (scale = 1)
// R4: 256 threads / CTA, M-tile 64, 2 CTAs per SM so barrier/LDSM shadows of
// one CTA overlap the other CTA's MMAs.
// ============================================================================

static constexpr int kV = 64;
static constexpr int kH = 128;
static constexpr int kMTile = 64;
static constexpr int kChunks = 41;
static constexpr int kChunkBytes = kH * kV * 2;   // 16384
static constexpr int kThreads = 256;

// smem layout (bytes, relative to 1024-aligned base)
static constexpr int SM_BIAS = 0;                  // 128 f32
static constexpr int SM_PART = 512;                // 64*4 f32 = 1024
static constexpr int SM_XS2  = 1536;               // 64*65 u32 = 16640
static constexpr int SM_XT   = 18432;              // 64x64 bf16 SW128 = 8192 (1024-al)
static constexpr int SM_B    = 27648;              // 3 * 16384 (1024-al)
static constexpr int SM_END  = SM_B + 3 * kChunkBytes;   // 76800
static constexpr int SMEM_TOTAL = SM_END + 1024;   // 77824 (x2 CTAs = 152K < 228K)

// Packed B operand: [chunk][h][64] bf16, cols = 4 k16-blocks per chunk.
__device__ __align__(16) __nv_bfloat16 g_wb[kChunks * kH * kV];

// ---------------------------------------------------------------------------
// helpers
// ---------------------------------------------------------------------------
__device__ __forceinline__ uint32_t smem_u32(const void* p) {
    uint32_t a;
    asm("{ .reg .u64 t; cvta.to.shared.u64 t, %1; cvt.u32.u64 %0, t; }"
        : "=r"(a) : "l"(p));
    return a;
}

#define SW128(o) ((o) ^ (((o) >> 3) & 0x70))

#define CVT_BF16X2(result, a, b) \
    asm("cvt.rn.bf16x2.f32 %0, %1, %2;" : "=r"(result) : "f"(b), "f"(a))

#define HMUL2(d, a, b) \
    asm("mul.rn.bf16x2 %0, %1, %2;" : "=r"(d) : "r"(a), "r"(b))

#define LDSM_X4(r0, r1, r2, r3, addr) \
    asm volatile("ldmatrix.sync.aligned.m8n8.x4.shared.b16 {%0,%1,%2,%3}, [%4];" \
        : "=r"(r0), "=r"(r1), "=r"(r2), "=r"(r3) : "r"(addr))

#define MMA16816(d, a0, a1, a2, a3, b0, b1) \
    asm volatile("mma.sync.aligned.m16n8k16.row.col.f32.bf16.bf16.f32 " \
        "{%0,%1,%2,%3}, {%4,%5,%6,%7}, {%8,%9}, {%0,%1,%2,%3};" \
        : "+f"((d)[0]), "+f"((d)[1]), "+f"((d)[2]), "+f"((d)[3]) \
        : "r"(a0), "r"(a1), "r"(a2), "r"(a3), "r"(b0), "r"(b1))

#define CP_ASYNC16(smem, gmem) \
    asm volatile("cp.async.cg.shared.global [%0], [%1], 16;" \
        :: "r"(smem), "l"(gmem) : "memory")
#define CP_COMMIT() asm volatile("cp.async.commit_group;" ::: "memory")
#define CP_WAIT1()  asm volatile("cp.async.wait_group 1;" ::: "memory")

__device__ __forceinline__ float cos_poly(float a) {
    // |a| < 0.1 guaranteed by problem statistics; deg-8 Taylor, err < 1e-12
    float t = a * a;
    return 1.0f + t * (-0.5f + t * (4.16666667e-2f +
               t * (-1.38888889e-3f + t * 2.48015873e-5f)));
}

// block schedule decode — used ONLY by the one-shot prep kernel
__device__ __forceinline__ int decode_i(int b) {
    if (b < 64)  return b >> 2;
    if (b < 112) return 16 + (b - 64) / 3;
    if (b < 144) return 32 + ((b - 112) >> 1);
    if (b < 160) return 48 + (b - 144);
    return 64;
}
__device__ __forceinline__ int decode_kbf(int b) {
    if (b < 64)  return b & 3;
    if (b < 112) return 1 + (b - 64) % 3;
    if (b < 144) return 2 + ((b - 112) & 1);
    if (b < 160) return 3;
    return b - 160;
}

// ---------------------------------------------------------------------------
// prep: build packed bf16 B operand g_wb from W2 (f32) + 2*W1^T (f32)
// ---------------------------------------------------------------------------
__global__ void __launch_bounds__(256) prep_kernel(const float* __restrict__ w2,
                                                   const float* __restrict__ w1) {
    int t = blockIdx.x * blockDim.x + threadIdx.x;
    int e = t * 4;
    if (e >= kChunks * kH * kV) return;
    int c   = e >> 13;
    int rem = e & 8191;
    int h   = rem >> 6;
    int col = rem & 63;
    int b   = 4 * c + (col >> 4);
    int i   = decode_i(b);
    int kbf = decode_kbf(b);
    int j0  = kbf * 16 + (col & 15);
    float v[4];
    #pragma unroll
    for (int q = 0; q < 4; q++) {
        int j = j0 + q;
        if (i == 64)     v[q] = 2.0f * w1[j * kH + h];
        else if (j > i)  v[q] = w2[h * 4096 + i * 64 + j] + w2[h * 4096 + j * 64 + i];
        else if (j == i) v[q] = w2[h * 4096 + i * 64 + j];
        else             v[q] = 0.0f;
    }
    uint32_t lo, hi;
    CVT_BF16X2(lo, v[0], v[1]);
    CVT_BF16X2(hi, v[2], v[3]);
    reinterpret_cast<uint2*>(g_wb)[t] = make_uint2(lo, hi);
}

// ---------------------------------------------------------------------------
// chunk body: kbf pattern + i-delta pattern are compile-time; ibase runtime
// ---------------------------------------------------------------------------
template<int K0, int K1, int K2, int K3, int D0, int D1, int D2, int D3, bool LIN>
__device__ __forceinline__ void do_chunk(
    uint32_t bb, const uint32_t* __restrict__ boff,
    const uint32_t (&abase)[2][4][4],
    const uint32_t* __restrict__ xs2, int ibase, int rb0,
    float (&acc)[2][4][4])
{
    const int KF[4] = {K0, K1, K2, K3};
    const int DI[4] = {D0, D1, D2, D3};
    #pragma unroll
    for (int kb = 0; kb < 4; kb++) {
        uint32_t sv[4];
        if (LIN) {
            sv[0] = sv[1] = sv[2] = sv[3] = 0x3F803F80u;   // bf16x2(1,1)
        } else {
            const uint32_t* row = xs2 + (ibase + DI[kb]) * 65 + rb0;
            sv[0] = row[0];  sv[1] = row[8];
            sv[2] = row[16]; sv[3] = row[24];
        }
        uint32_t bf[4][2];
        LDSM_X4(bf[0][0], bf[0][1], bf[1][0], bf[1][1], bb + boff[kb * 2 + 0]);
        LDSM_X4(bf[2][0], bf[2][1], bf[3][0], bf[3][1], bb + boff[kb * 2 + 1]);
        #pragma unroll
        for (int mb = 0; mb < 2; mb++) {
            uint32_t t0, t1, t2, t3;
            HMUL2(t0, abase[mb][KF[kb]][0], sv[2 * mb]);      // rows g
            HMUL2(t1, abase[mb][KF[kb]][1], sv[2 * mb + 1]);  // rows g+8
            HMUL2(t2, abase[mb][KF[kb]][2], sv[2 * mb]);
            HMUL2(t3, abase[mb][KF[kb]][3], sv[2 * mb + 1]);
            #pragma unroll
            for (int nb = 0; nb < 4; nb++)
                MMA16816(acc[mb][nb], t0, t1, t2, t3, bf[nb][0], bf[nb][1]);
        }
    }
}

// ---------------------------------------------------------------------------
// main fused kernel: 64-row M-tile per CTA, H=128 as N, 8 warps (2M x 4N),
// 2 CTAs per SM
// ---------------------------------------------------------------------------
__global__ void __launch_bounds__(kThreads, 2)
rbm_main_kernel(const float* __restrict__ x,
                const float* __restrict__ bias,
                float* __restrict__ out) {
    extern __shared__ char smem_raw[];
    char* sm = (char*)((((uintptr_t)smem_raw) + 1023) & ~(uintptr_t)1023);
    const uint32_t sb = smem_u32(sm);
    const int tid = threadIdx.x;
    const int l   = tid & 31;
    const int w   = tid >> 5;
    const int g   = l >> 2;
    const int t4  = l & 3;
    const int wm  = (w >> 2) * 32;     // warp M offset (0,32)
    const int wn  = (w & 3) * 32;      // warp N offset (0,32,64,96)
    const int m0  = blockIdx.x * kMTile;

    float*    sbias = (float*)(sm + SM_BIAS);
    float*    spart = (float*)(sm + SM_PART);
    uint32_t* xs2   = (uint32_t*)(sm + SM_XS2);   // [j][m] bf16x2 bcast, pitch 65

    if (tid < kH) sbias[tid] = bias[tid];

    // --- x bf16 tile [m][j], 128B rows, SW128 swizzled (A ldmatrix source) ---
    {
        const float4* x4 = (const float4*)(x + (size_t)m0 * kV);
        #pragma unroll
        for (int e = tid; e < kMTile * 16; e += kThreads) {   // 64 rows * 16 float4
            int r = e >> 4, q = e & 15;
            float4 f = x4[e];
            uint32_t u0, u1;
            CVT_BF16X2(u0, f.x, f.y);
            CVT_BF16X2(u1, f.z, f.w);
            uint32_t off = (uint32_t)(r * 128 + q * 8);
            *(uint2*)(sm + SM_XT + SW128(off)) = make_uint2(u0, u1);
        }
    }
    // --- xs2[j][m] = bf16x2(x[m,j], x[m,j]) broadcast scalars ---
    #pragma unroll
    for (int e = tid; e < kV * kMTile; e += kThreads) {
        int m = e >> 6, j = e & 63;
        float v = x[(size_t)(m0 + m) * kV + j];
        uint32_t p;
        CVT_BF16X2(p, v, v);
        xs2[j * 65 + m] = p;
    }

    // --- cp.async B prefetch (3 buffers, distance 2); 4 x 16B per thread ---
    const char* gw = (const char*)g_wb;
    #define ISSUE_CHUNK(c, buf) do {                                          \
        const char* _src = gw + (size_t)(c) * kChunkBytes;                    \
        uint32_t _dst = sb + SM_B + (uint32_t)(buf) * kChunkBytes;            \
        _Pragma("unroll")                                                     \
        for (int _p = 0; _p < 4; _p++) {                                      \
            int _cg = tid + _p * kThreads;                                    \
            uint32_t _off = (uint32_t)((_cg >> 3) * 128 + (_cg & 7) * 16);    \
            CP_ASYNC16(_dst + SW128(_off), _src + _off);                      \
        }                                                                     \
    } while (0)

    ISSUE_CHUNK(0, 0); CP_COMMIT();
    ISSUE_CHUNK(1, 1); CP_COMMIT();

    __syncthreads();   // x tiles + bias ready

    // --- A-base fragments (warp's 32x64 x-tile) in registers ---
    uint32_t abase[2][4][4];
    {
        int q = l >> 3, rr = l & 7;
        #pragma unroll
        for (int mb = 0; mb < 2; mb++)
        #pragma unroll
        for (int kb = 0; kb < 4; kb++) {
            uint32_t off = (uint32_t)((wm + 16 * mb + (q & 1) * 8 + rr) * 128
                                      + (kb * 16 + (q >> 1) * 8) * 2);
            LDSM_X4(abase[mb][kb][0], abase[mb][kb][1],
                    abase[mb][kb][2], abase[mb][kb][3],
                    sb + SM_XT + SW128(off));
        }
    }

    // --- per-thread B ldmatrix offsets (swizzled, rel. to buffer base) ---
    uint32_t boff[8];
    {
        int q = l >> 3, rr = l & 7;
        #pragma unroll
        for (int kb = 0; kb < 4; kb++)
        #pragma unroll
        for (int nb2 = 0; nb2 < 2; nb2++) {
            uint32_t off = (uint32_t)((wn + nb2 * 16 + (q >> 1) * 8 + rr) * 128
                                      + (kb * 16 + (q & 1) * 8) * 2);
            boff[kb * 2 + nb2] = SW128(off);
        }
    }

    float acc[2][4][4];
    #pragma unroll
    for (int a = 0; a < 2; a++)
    #pragma unroll
    for (int b = 0; b < 4; b++)
    #pragma unroll
    for (int c = 0; c < 4; c++) acc[a][b][c] = 0.0f;

    const int rb0 = wm + g;

    // pipeline step: wait chunk c, release buffer (c+2)%3, prefetch c+2, run body
    int c = 0;
    #define PIPE(BODY) do {                                                   \
        CP_WAIT1();                                                           \
        __syncthreads();                                                      \
        if (c + 2 < kChunks) { ISSUE_CHUNK(c + 2, (c + 2) % 3); }             \
        CP_COMMIT();                                                          \
        uint32_t bb = sb + SM_B + (uint32_t)(c % 3) * kChunkBytes;            \
        BODY;                                                                 \
        c++;                                                                  \
    } while (0)

    // Region A: i = c, kbf 0..3
    #pragma unroll 1
    for (int cc = 0; cc < 16; cc++) {
        PIPE((do_chunk<0,1,2,3, 0,0,0,0, false>(bb, boff, abase, xs2, cc, rb0, acc)));
    }
    // Region B: 3-chunk period, i 16..31
    int I = 16;
    #pragma unroll 1
    for (int r = 0; r < 4; r++) {
        PIPE((do_chunk<1,2,3,1, 0,0,0,1, false>(bb, boff, abase, xs2, I,     rb0, acc)));
        PIPE((do_chunk<2,3,1,2, 0,0,1,1, false>(bb, boff, abase, xs2, I + 1, rb0, acc)));
        PIPE((do_chunk<3,1,2,3, 0,1,1,1, false>(bb, boff, abase, xs2, I + 2, rb0, acc)));
        I += 4;
    }
    // Region C: i 32..47
    #pragma unroll 1
    for (int r = 0; r < 8; r++) {
        PIPE((do_chunk<2,3,2,3, 0,0,1,1, false>(bb, boff, abase, xs2, I, rb0, acc)));
        I += 2;
    }
    // Region D: i 48..63
    #pragma unroll 1
    for (int r = 0; r < 4; r++) {
        PIPE((do_chunk<3,3,3,3, 0,1,2,3, false>(bb, boff, abase, xs2, I, rb0, acc)));
        I += 4;
    }
    // Region E: linear term
    PIPE((do_chunk<0,1,2,3, 0,0,0,0, true>(bb, boff, abase, xs2, 0, rb0, acc)));

    // --- epilogue: a = bias + 0.5*acc; psi = prod cos(a) ---
    #pragma unroll
    for (int mb = 0; mb < 2; mb++) {
        float p0 = 1.0f, p1 = 1.0f;
        #pragma unroll
        for (int nb = 0; nb < 4; nb++) {
            int col = wn + nb * 8 + 2 * t4;
            #pragma unroll
            for (int cc = 0; cc < 2; cc++) {
                float bv = sbias[col + cc];
                p0 *= cos_poly(bv + 0.5f * acc[mb][nb][cc]);       // row g
                p1 *= cos_poly(bv + 0.5f * acc[mb][nb][2 + cc]);   // row g+8
            }
        }
        p0 *= __shfl_xor_sync(0xFFFFFFFFu, p0, 1);
        p0 *= __shfl_xor_sync(0xFFFFFFFFu, p0, 2);
        p1 *= __shfl_xor_sync(0xFFFFFFFFu, p1, 1);
        p1 *= __shfl_xor_sync(0xFFFFFFFFu, p1, 2);
        if (t4 == 0) {
            spart[(rb0 + 16 * mb) * 4 + (w & 3)]     = p0;
            spart[(rb0 + 16 * mb + 8) * 4 + (w & 3)] = p1;
        }
    }
    __syncthreads();
    if (tid < kMTile) {
        out[m0 + tid] = spart[tid * 4 + 0] * spart[tid * 4 + 1]
                      * spart[tid * 4 + 2] * spart[tid * 4 + 3];
    }
}

// ---------------------------------------------------------------------------
// launch
// ---------------------------------------------------------------------------
extern "C" void kernel_launch(void* const* d_in, const int* in_sizes, int n_in,
                              void* d_out, int out_size) {
    const float* x    = (const float*)d_in[0];   // (16384, 64)
    const float* w1   = (const float*)d_in[1];   // (64, 128)
    const float* w2   = (const float*)d_in[2];   // (128, 64, 64)
    const float* bias = (const float*)d_in[3];   // (128,)
    float* out = (float*)d_out;                  // (16384,)

    cudaFuncSetAttribute(rbm_main_kernel,
                         cudaFuncAttributeMaxDynamicSharedMemorySize, SMEM_TOTAL);

    prep_kernel<<<328, 256>>>(w2, w1);           // 41*8192/4/256
    rbm_main_kernel<<<16384 / kMTile, kThreads, SMEM_TOTAL>>>(x, bias, out);
}